// round 12
// baseline (speedup 1.0000x reference)
#include <cuda_runtime.h>
#include <cuda_bf16.h>
#include <cstdint>

// Problem constants
#define B_  8
#define T_  1024
#define S_  1024
#define H_  1024
#define V_  5000
#define M_  (B_ * T_)   // 8192 rows
#define VPAD 5120       // V padded to multiple of 128

// Scratch (static device globals — allocation-free)
__device__ __nv_bfloat16 g_xb[(size_t)M_ * H_];    // x in bf16, 16 MB
__device__ __nv_bfloat16 g_hb[(size_t)M_ * H_];    // gelu(x@Wf+bf) in bf16, 16 MB
__device__ float g_pgen[M_];                       // sigmoid(x@Wg + bg)
__device__ __nv_bfloat16 g_WfTb[(size_t)H_ * H_];  // Wf^T bf16 [N=H][K=H]
__device__ __nv_bfloat16 g_WvTb[(size_t)VPAD * H_];// Wv^T bf16 [N=VPAD][K=H], padded

// ---------------------------------------------------------------------------
// helpers
// ---------------------------------------------------------------------------
__device__ __forceinline__ uint32_t smem_u32(const void* p) {
    return (uint32_t)__cvta_generic_to_shared(p);
}
__device__ __forceinline__ void cp_async16(uint32_t dst, const void* src) {
    asm volatile("cp.async.cg.shared.global [%0], [%1], 16;" :: "r"(dst), "l"(src));
}
__device__ __forceinline__ void cp_commit() {
    asm volatile("cp.async.commit_group;" ::: "memory");
}
template <int N>
__device__ __forceinline__ void cp_wait() {
    asm volatile("cp.async.wait_group %0;" :: "n"(N) : "memory");
}

// m16n8k16 bf16 mma (sm_80+)
__device__ __forceinline__ void mma_bf16(float& d0, float& d1, float& d2, float& d3,
                                         uint32_t a0, uint32_t a1, uint32_t a2, uint32_t a3,
                                         uint32_t b0, uint32_t b1) {
    asm volatile(
        "mma.sync.aligned.m16n8k16.row.col.f32.bf16.bf16.f32 "
        "{%0,%1,%2,%3}, {%4,%5,%6,%7}, {%8,%9}, {%0,%1,%2,%3};"
        : "+f"(d0), "+f"(d1), "+f"(d2), "+f"(d3)
        : "r"(a0), "r"(a1), "r"(a2), "r"(a3), "r"(b0), "r"(b1));
}

__device__ __forceinline__ void ldsm_x4(uint32_t& r0, uint32_t& r1, uint32_t& r2, uint32_t& r3,
                                        uint32_t addr) {
    asm volatile("ldmatrix.sync.aligned.m8n8.x4.shared.b16 {%0,%1,%2,%3}, [%4];"
                 : "=r"(r0), "=r"(r1), "=r"(r2), "=r"(r3) : "r"(addr));
}

__device__ __forceinline__ float gelu_tanh(float v) {
    const float c = 0.7978845608028654f;   // sqrt(2/pi)
    float u = c * (v + 0.044715f * v * v * v);
    return 0.5f * v * (1.f + tanhf(u));
}

// ---------------------------------------------------------------------------
// Transpose fp32 -> bf16, 32x32 tiles, zero-pad rows beyond C.
// ---------------------------------------------------------------------------
__global__ void transpose_bf16_kernel(const float* __restrict__ W, __nv_bfloat16* __restrict__ Wt,
                                      int R, int C, int Cpad) {
    __shared__ float t[32][33];
    int c0 = blockIdx.x * 32;
    int r0 = blockIdx.y * 32;
    #pragma unroll
    for (int k = 0; k < 4; k++) {
        int r = r0 + threadIdx.y + k * 8;
        int c = c0 + threadIdx.x;
        float v = 0.f;
        if (r < R && c < C) v = W[(size_t)r * C + c];
        t[threadIdx.y + k * 8][threadIdx.x] = v;
    }
    __syncthreads();
    #pragma unroll
    for (int k = 0; k < 4; k++) {
        int rr = c0 + threadIdx.y + k * 8;
        int cc = r0 + threadIdx.x;
        if (rr < Cpad && cc < R)
            Wt[(size_t)rr * R + cc] = __float2bfloat16_rn(t[threadIdx.x][threadIdx.y + k * 8]);
    }
}

// ---------------------------------------------------------------------------
// Fused: p_gen = sigmoid(x @ Wg + bg)  AND  xb = bf16(x)
// ---------------------------------------------------------------------------
__global__ __launch_bounds__(256)
void pgen_cvt_kernel(const float* __restrict__ x,
                     const float* __restrict__ Wg,
                     const float* __restrict__ bg,
                     float* __restrict__ pgen,
                     __nv_bfloat16* __restrict__ xb) {
    int r = blockIdx.x;
    const float* xr = x + (size_t)r * H_;
    __nv_bfloat16* xbr = xb + (size_t)r * H_;

    float s = 0.f;
    for (int i = threadIdx.x; i < H_ / 4; i += 256) {
        float4 v = ((const float4*)xr)[i];
        float4 w = ((const float4*)Wg)[i];
        s += v.x * w.x + v.y * w.y + v.z * w.z + v.w * w.w;
        __nv_bfloat162 p0, p1;
        p0.x = __float2bfloat16_rn(v.x); p0.y = __float2bfloat16_rn(v.y);
        p1.x = __float2bfloat16_rn(v.z); p1.y = __float2bfloat16_rn(v.w);
        ((__nv_bfloat162*)xbr)[2 * i]     = p0;
        ((__nv_bfloat162*)xbr)[2 * i + 1] = p1;
    }
    __shared__ float red[8];
    #pragma unroll
    for (int o = 16; o; o >>= 1) s += __shfl_xor_sync(0xFFFFFFFFu, s, o);
    if ((threadIdx.x & 31) == 0) red[threadIdx.x >> 5] = s;
    __syncthreads();
    if (threadIdx.x < 8) {
        s = red[threadIdx.x];
        #pragma unroll
        for (int o = 4; o; o >>= 1) s += __shfl_xor_sync(0xFFu, s, o);
        if (threadIdx.x == 0) {
            float z = s + bg[0];
            pgen[r] = 1.f / (1.f + expf(-z));
        }
    }
}

// ---------------------------------------------------------------------------
// bf16 mma.sync GEMM: C = epi(A[M,K] @ Bt[N,K]^T + bias[N])
// BM=64, BN=128, BK=32 bf16, 256 threads (8 warps 2x4), warp tile 32x32.
// ~70 regs/thread -> 3 CTAs/SM (24 warps, 37.5% occ) for latency hiding.
// 4-stage cp.async ring, one wait+sync per iteration.
// SMEM rows padded to 40 bf16 -> conflict-free LDSM.
// EPI 0: gelu -> bf16 out.  EPI 1: identity -> fp32 out (ragged N).
// ---------------------------------------------------------------------------
#define BM 64
#define BN 128
#define BK 32
#define KP2 40
#define A_STAGE_B (BM * KP2 * 2)              // 5120 B
#define B_STAGE_B (BN * KP2 * 2)              // 10240 B
#define STAGE_B   (A_STAGE_B + B_STAGE_B)     // 15360 B
#define NSTAGE 4
#define DYNSMEM2 (NSTAGE * STAGE_B)           // 61440 B (3 CTAs = 184 KB/SM)

template <int EPI, typename OutT>
__global__ __launch_bounds__(256, 3)
void bf16_gemm_kernel(const __nv_bfloat16* __restrict__ A,
                      const __nv_bfloat16* __restrict__ Bt,
                      const float* __restrict__ bias, OutT* __restrict__ C,
                      int Nreal, int K) {
    extern __shared__ char sm2[];
    uint32_t base = smem_u32(sm2);
    uint32_t AsO[NSTAGE], BsO[NSTAGE];
    #pragma unroll
    for (int s = 0; s < NSTAGE; s++) {
        AsO[s] = base + (uint32_t)s * STAGE_B;
        BsO[s] = AsO[s] + A_STAGE_B;
    }

    const int tid  = threadIdx.x;
    const int wid  = tid >> 5;
    const int lane = tid & 31;
    const int g    = lane >> 2;
    const int t    = lane & 3;
    const int wm   = (wid >> 2) * 32;    // 0 or 32
    const int wn   = (wid & 3) * 32;     // 0,32,64,96

    const int rowBase = blockIdx.y * BM;
    const int colBase = blockIdx.x * BN;
    const int NK = K / BK;               // 32

    const __nv_bfloat16* Abase = A  + (size_t)rowBase * K;
    const __nv_bfloat16* Bbase = Bt + (size_t)colBase * K;

    float acc[2][4][4];
    #pragma unroll
    for (int i = 0; i < 2; i++)
        #pragma unroll
        for (int j = 0; j < 4; j++)
            #pragma unroll
            for (int r = 0; r < 4; r++) acc[i][j][r] = 0.f;

    // per-stage loader: A 64 rows x 64B = 256 chunks; B 128 rows = 512 chunks
    auto load_stage = [&](int st, int k0) {
        {
            int r = tid >> 2;               // 0..63
            int c = tid & 3;
            uint32_t off = (uint32_t)(r * (KP2 * 2) + c * 16);
            cp_async16(AsO[st] + off, Abase + (size_t)r * K + k0 + c * 8);
        }
        #pragma unroll
        for (int i = 0; i < 2; i++) {
            int idx = tid + i * 256;        // 0..511
            int r   = idx >> 2;             // 0..127
            int c   = idx & 3;
            uint32_t off = (uint32_t)(r * (KP2 * 2) + c * 16);
            cp_async16(BsO[st] + off, Bbase + (size_t)r * K + k0 + c * 8);
        }
        cp_commit();
    };

    // ldmatrix per-thread address components
    const uint32_t aRowOff = (uint32_t)(lane & 15) * (KP2 * 2);
    const uint32_t aKh     = (uint32_t)(lane >> 4) * 16;
    const uint32_t bRowOff = (uint32_t)((lane & 7) + ((lane >> 4) << 3)) * (KP2 * 2);
    const uint32_t bKh     = (uint32_t)((lane >> 3) & 1) * 16;

    // prologue: stages 0,1,2 (3 groups in flight)
    load_stage(0, 0);
    load_stage(1, BK);
    load_stage(2, 2 * BK);

    for (int it = 0; it < NK; it++) {
        int st = it % NSTAGE;
        if (it + 2 < NK)      { cp_wait<2>(); }
        else if (it + 1 < NK) { cp_wait<1>(); }
        else                  { cp_wait<0>(); }
        __syncthreads();   // stage it ready AND slot (it+3)%4 free

        if (it + 3 < NK) load_stage((it + 3) % NSTAGE, (it + 3) * BK);

        uint32_t as = AsO[st];
        uint32_t bs = BsO[st];

        #pragma unroll
        for (int kk = 0; kk < 2; kk++) {   // two k16 steps
            uint32_t kb = kk * 32;
            uint32_t afr[2][4];
            #pragma unroll
            for (int mt = 0; mt < 2; mt++)
                ldsm_x4(afr[mt][0], afr[mt][1], afr[mt][2], afr[mt][3],
                        as + (uint32_t)(wm + mt * 16) * (KP2 * 2) + aRowOff + kb + aKh);
            uint32_t bfr[4][2];
            #pragma unroll
            for (int p = 0; p < 2; p++) {
                uint32_t r0, r1, r2, r3;
                ldsm_x4(r0, r1, r2, r3,
                        bs + (uint32_t)(wn + p * 16) * (KP2 * 2) + bRowOff + kb + bKh);
                bfr[2 * p][0]     = r0; bfr[2 * p][1]     = r1;
                bfr[2 * p + 1][0] = r2; bfr[2 * p + 1][1] = r3;
            }
            #pragma unroll
            for (int mt = 0; mt < 2; mt++)
                #pragma unroll
                for (int nt = 0; nt < 4; nt++)
                    mma_bf16(acc[mt][nt][0], acc[mt][nt][1],
                             acc[mt][nt][2], acc[mt][nt][3],
                             afr[mt][0], afr[mt][1], afr[mt][2], afr[mt][3],
                             bfr[nt][0], bfr[nt][1]);
        }
    }

    // epilogue
    #pragma unroll
    for (int mt = 0; mt < 2; mt++) {
        int row0 = rowBase + wm + mt * 16 + g;
        OutT* crow0 = C + (size_t)row0 * Nreal;
        OutT* crow1 = C + (size_t)(row0 + 8) * Nreal;
        #pragma unroll
        for (int nt = 0; nt < 4; nt++) {
            int col0 = colBase + wn + nt * 8 + 2 * t;
            if constexpr (EPI == 0) {
                float b0 = bias[col0], b1 = bias[col0 + 1];
                float v0 = gelu_tanh(acc[mt][nt][0] + b0);
                float v1 = gelu_tanh(acc[mt][nt][1] + b1);
                float v2 = gelu_tanh(acc[mt][nt][2] + b0);
                float v3 = gelu_tanh(acc[mt][nt][3] + b1);
                __nv_bfloat162 p0, p1;
                p0.x = __float2bfloat16_rn(v0); p0.y = __float2bfloat16_rn(v1);
                p1.x = __float2bfloat16_rn(v2); p1.y = __float2bfloat16_rn(v3);
                *(__nv_bfloat162*)&crow0[col0] = p0;
                *(__nv_bfloat162*)&crow1[col0] = p1;
            } else {
                if (col0 + 1 < Nreal) {
                    float b0 = bias[col0], b1 = bias[col0 + 1];
                    float2 p0 = make_float2(acc[mt][nt][0] + b0, acc[mt][nt][1] + b1);
                    float2 p1 = make_float2(acc[mt][nt][2] + b0, acc[mt][nt][3] + b1);
                    *(float2*)&crow0[col0] = p0;
                    *(float2*)&crow1[col0] = p1;
                } else if (col0 < Nreal) {
                    float b0 = bias[col0];
                    crow0[col0] = acc[mt][nt][0] + b0;
                    crow1[col0] = acc[mt][nt][2] + b0;
                }
            }
        }
    }
}

// ---------------------------------------------------------------------------
// per-row softmax * p_gen + shared-memory scatter-add, write out.
// scale folded into write-back; scatter adds pre-divided mass.
// ---------------------------------------------------------------------------
#define SMT 512
__global__ __launch_bounds__(SMT)
void softmax_scatter_kernel(const float* __restrict__ attn,
                            const int*   __restrict__ nodes,
                            const float* __restrict__ pgen,
                            float* __restrict__ out) {
    __shared__ float srow[V_];
    __shared__ float red[17];

    const int r   = blockIdx.x;
    const int b   = r / T_;
    const int tid = threadIdx.x;
    float* orow   = out + (size_t)r * V_;
    const int nwarp = SMT / 32;

    float mx = -3.0e38f;
    for (int i = tid; i < V_ / 4; i += SMT) {
        float4 v = ((const float4*)orow)[i];
        ((float4*)srow)[i] = v;
        mx = fmaxf(fmaxf(mx, fmaxf(v.x, v.y)), fmaxf(v.z, v.w));
    }
    #pragma unroll
    for (int o = 16; o; o >>= 1) mx = fmaxf(mx, __shfl_xor_sync(0xFFFFFFFFu, mx, o));
    if ((tid & 31) == 0) red[tid >> 5] = mx;
    __syncthreads();
    if (tid < nwarp) {
        float v = red[tid];
        #pragma unroll
        for (int o = 8; o; o >>= 1) v = fmaxf(v, __shfl_xor_sync(0xFFFFu, v, o));
        if (tid == 0) red[16] = v;
    }
    __syncthreads();
    mx = red[16];

    float sum = 0.f;
    for (int i = tid; i < V_ / 4; i += SMT) {
        float4 v = ((float4*)srow)[i];
        v.x = __expf(v.x - mx); v.y = __expf(v.y - mx);
        v.z = __expf(v.z - mx); v.w = __expf(v.w - mx);
        ((float4*)srow)[i] = v;
        sum += v.x + v.y + v.z + v.w;
    }
    __syncthreads();
    #pragma unroll
    for (int o = 16; o; o >>= 1) sum += __shfl_xor_sync(0xFFFFFFFFu, sum, o);
    if ((tid & 31) == 0) red[tid >> 5] = sum;
    __syncthreads();
    if (tid < nwarp) {
        float v = red[tid];
        #pragma unroll
        for (int o = 8; o; o >>= 1) v += __shfl_xor_sync(0xFFFFu, v, o);
        if (tid == 0) red[16] = v;
    }
    __syncthreads();
    sum = red[16];

    const float pg    = pgen[r];
    const float scale = pg / sum;                 // final multiplier
    const float caddf = (1.f - pg) * sum / pg;    // pre-divided pointer mass

    const float* ar = attn  + (size_t)r * S_;
    const int*   nb = nodes + (size_t)b * S_;
    for (int i = tid; i < S_ / 4; i += SMT) {
        float4 av = ((const float4*)ar)[i];
        int4   nv = ((const int4*)nb)[i];
        atomicAdd(&srow[nv.x], av.x * caddf);
        atomicAdd(&srow[nv.y], av.y * caddf);
        atomicAdd(&srow[nv.z], av.z * caddf);
        atomicAdd(&srow[nv.w], av.w * caddf);
    }
    __syncthreads();

    for (int i = tid; i < V_ / 4; i += SMT) {
        float4 v = ((const float4*)srow)[i];
        v.x *= scale; v.y *= scale; v.z *= scale; v.w *= scale;
        ((float4*)orow)[i] = v;
    }
}

// ---------------------------------------------------------------------------
// Launch
// ---------------------------------------------------------------------------
extern "C" void kernel_launch(void* const* d_in, const int* in_sizes, int n_in,
                              void* d_out, int out_size) {
    const float* x    = (const float*)d_in[0];
    const float* attn = (const float*)d_in[1];
    const int*   nodes= (const int*)  d_in[2];
    const float* Wg   = (const float*)d_in[3];
    const float* bg   = (const float*)d_in[4];
    const float* Wf   = (const float*)d_in[5];
    const float* bf   = (const float*)d_in[6];
    const float* Wv   = (const float*)d_in[7];
    const float* bv   = (const float*)d_in[8];
    float* out        = (float*)d_out;

    __nv_bfloat16* xb;   cudaGetSymbolAddress((void**)&xb,   g_xb);
    __nv_bfloat16* hb;   cudaGetSymbolAddress((void**)&hb,   g_hb);
    float* pgen;         cudaGetSymbolAddress((void**)&pgen, g_pgen);
    __nv_bfloat16* WfTb; cudaGetSymbolAddress((void**)&WfTb, g_WfTb);
    __nv_bfloat16* WvTb; cudaGetSymbolAddress((void**)&WvTb, g_WvTb);

    cudaFuncSetAttribute((const void*)bf16_gemm_kernel<0, __nv_bfloat16>,
                         cudaFuncAttributeMaxDynamicSharedMemorySize, DYNSMEM2);
    cudaFuncSetAttribute((const void*)bf16_gemm_kernel<1, float>,
                         cudaFuncAttributeMaxDynamicSharedMemorySize, DYNSMEM2);

    // prep: weight transposes (bf16, K-major)
    transpose_bf16_kernel<<<dim3(H_ / 32, H_ / 32), dim3(32, 8)>>>(Wf, WfTb, H_, H_, H_);
    transpose_bf16_kernel<<<dim3(VPAD / 32, H_ / 32), dim3(32, 8)>>>(Wv, WvTb, H_, V_, VPAD);

    // p_gen (fp32 dot) + x -> bf16 (fused)
    pgen_cvt_kernel<<<M_, 256>>>(x, Wg, bg, pgen, xb);

    // h_bf16 = gelu(x @ Wf + bf)
    bf16_gemm_kernel<0, __nv_bfloat16><<<dim3(H_ / BN, M_ / BM), 256, DYNSMEM2>>>(
        xb, WfTb, bf, hb, H_, H_);

    // logits = h_bf @ Wv + bv -> d_out
    bf16_gemm_kernel<1, float><<<dim3(VPAD / BN, M_ / BM), 256, DYNSMEM2>>>(
        hb, WvTb, bv, out, V_, H_);

    // softmax * p_gen + pointer scatter
    softmax_scatter_kernel<<<M_, SMT>>>(attn, nodes, pgen, out);
}

// round 13
// speedup vs baseline: 1.1034x; 1.1034x over previous
#include <cuda_runtime.h>
#include <cuda_bf16.h>
#include <cstdint>

// Problem constants
#define B_  8
#define T_  1024
#define S_  1024
#define H_  1024
#define V_  5000
#define M_  (B_ * T_)   // 8192 rows
#define VPAD 5120       // V padded to multiple of 128

// Scratch (static device globals — allocation-free)
__device__ __nv_bfloat16 g_xb[(size_t)M_ * H_];    // x in bf16, 16 MB
__device__ __nv_bfloat16 g_hb[(size_t)M_ * H_];    // gelu(x@Wf+bf) in bf16, 16 MB
__device__ __nv_bfloat16 g_lb[(size_t)M_ * V_];    // logits bf16, 78 MB
__device__ float g_pgen[M_];                       // sigmoid(x@Wg + bg)
__device__ __nv_bfloat16 g_WfTb[(size_t)H_ * H_];  // Wf^T bf16 [N=H][K=H]
__device__ __nv_bfloat16 g_WvTb[(size_t)VPAD * H_];// Wv^T bf16 [N=VPAD][K=H], padded

// ---------------------------------------------------------------------------
// helpers
// ---------------------------------------------------------------------------
__device__ __forceinline__ uint32_t smem_u32(const void* p) {
    return (uint32_t)__cvta_generic_to_shared(p);
}
__device__ __forceinline__ void cp_async16(uint32_t dst, const void* src) {
    asm volatile("cp.async.cg.shared.global [%0], [%1], 16;" :: "r"(dst), "l"(src));
}
__device__ __forceinline__ void cp_commit() {
    asm volatile("cp.async.commit_group;" ::: "memory");
}
template <int N>
__device__ __forceinline__ void cp_wait() {
    asm volatile("cp.async.wait_group %0;" :: "n"(N) : "memory");
}

// m16n8k16 bf16 mma (sm_80+)
__device__ __forceinline__ void mma_bf16(float& d0, float& d1, float& d2, float& d3,
                                         uint32_t a0, uint32_t a1, uint32_t a2, uint32_t a3,
                                         uint32_t b0, uint32_t b1) {
    asm volatile(
        "mma.sync.aligned.m16n8k16.row.col.f32.bf16.bf16.f32 "
        "{%0,%1,%2,%3}, {%4,%5,%6,%7}, {%8,%9}, {%0,%1,%2,%3};"
        : "+f"(d0), "+f"(d1), "+f"(d2), "+f"(d3)
        : "r"(a0), "r"(a1), "r"(a2), "r"(a3), "r"(b0), "r"(b1));
}

__device__ __forceinline__ void ldsm_x4(uint32_t& r0, uint32_t& r1, uint32_t& r2, uint32_t& r3,
                                        uint32_t addr) {
    asm volatile("ldmatrix.sync.aligned.m8n8.x4.shared.b16 {%0,%1,%2,%3}, [%4];"
                 : "=r"(r0), "=r"(r1), "=r"(r2), "=r"(r3) : "r"(addr));
}

__device__ __forceinline__ float gelu_tanh(float v) {
    const float c = 0.7978845608028654f;   // sqrt(2/pi)
    float u = c * (v + 0.044715f * v * v * v);
    return 0.5f * v * (1.f + tanhf(u));
}

// ---------------------------------------------------------------------------
// Transpose fp32 -> bf16, 32x32 tiles, zero-pad rows beyond C.
// ---------------------------------------------------------------------------
__global__ void transpose_bf16_kernel(const float* __restrict__ W, __nv_bfloat16* __restrict__ Wt,
                                      int R, int C, int Cpad) {
    __shared__ float t[32][33];
    int c0 = blockIdx.x * 32;
    int r0 = blockIdx.y * 32;
    #pragma unroll
    for (int k = 0; k < 4; k++) {
        int r = r0 + threadIdx.y + k * 8;
        int c = c0 + threadIdx.x;
        float v = 0.f;
        if (r < R && c < C) v = W[(size_t)r * C + c];
        t[threadIdx.y + k * 8][threadIdx.x] = v;
    }
    __syncthreads();
    #pragma unroll
    for (int k = 0; k < 4; k++) {
        int rr = c0 + threadIdx.y + k * 8;
        int cc = r0 + threadIdx.x;
        if (rr < Cpad && cc < R)
            Wt[(size_t)rr * R + cc] = __float2bfloat16_rn(t[threadIdx.x][threadIdx.y + k * 8]);
    }
}

// ---------------------------------------------------------------------------
// Fused: p_gen = sigmoid(x @ Wg + bg)  AND  xb = bf16(x)
// ---------------------------------------------------------------------------
__global__ __launch_bounds__(256)
void pgen_cvt_kernel(const float* __restrict__ x,
                     const float* __restrict__ Wg,
                     const float* __restrict__ bg,
                     float* __restrict__ pgen,
                     __nv_bfloat16* __restrict__ xb) {
    int r = blockIdx.x;
    const float* xr = x + (size_t)r * H_;
    __nv_bfloat16* xbr = xb + (size_t)r * H_;

    float s = 0.f;
    for (int i = threadIdx.x; i < H_ / 4; i += 256) {
        float4 v = ((const float4*)xr)[i];
        float4 w = ((const float4*)Wg)[i];
        s += v.x * w.x + v.y * w.y + v.z * w.z + v.w * w.w;
        __nv_bfloat162 p0, p1;
        p0.x = __float2bfloat16_rn(v.x); p0.y = __float2bfloat16_rn(v.y);
        p1.x = __float2bfloat16_rn(v.z); p1.y = __float2bfloat16_rn(v.w);
        ((__nv_bfloat162*)xbr)[2 * i]     = p0;
        ((__nv_bfloat162*)xbr)[2 * i + 1] = p1;
    }
    __shared__ float red[8];
    #pragma unroll
    for (int o = 16; o; o >>= 1) s += __shfl_xor_sync(0xFFFFFFFFu, s, o);
    if ((threadIdx.x & 31) == 0) red[threadIdx.x >> 5] = s;
    __syncthreads();
    if (threadIdx.x < 8) {
        s = red[threadIdx.x];
        #pragma unroll
        for (int o = 4; o; o >>= 1) s += __shfl_xor_sync(0xFFu, s, o);
        if (threadIdx.x == 0) {
            float z = s + bg[0];
            pgen[r] = 1.f / (1.f + expf(-z));
        }
    }
}

// ---------------------------------------------------------------------------
// bf16 mma.sync GEMM (round-11 config): C = epi(A[M,K] @ Bt[N,K]^T + bias[N])
// BM=BN=128, BK=32 bf16, 256 threads (8 warps 2x4), warp tile 64x32.
// 5-stage cp.async ring, one wait+sync per TWO k-iterations, k16 ping-pong.
// SMEM rows padded to 40 bf16 -> conflict-free LDSM.
// EPI 0: gelu -> bf16 out.  EPI 1: bias only -> bf16 out (ragged N).
// ---------------------------------------------------------------------------
#define BM 128
#define BN 128
#define BK 32
#define KP2 40
#define STAGE2_BYTES (128 * KP2 * 2)          // 10240 B per operand per stage
#define NSTAGE 5
#define DYNSMEM2 (NSTAGE * 2 * STAGE2_BYTES)  // 102400 B (2 CTAs = 204.8 KB/SM)

template <int EPI>
__global__ __launch_bounds__(256, 2)
void bf16_gemm_kernel(const __nv_bfloat16* __restrict__ A,
                      const __nv_bfloat16* __restrict__ Bt,
                      const float* __restrict__ bias, __nv_bfloat16* __restrict__ C,
                      int Nreal, int K) {
    extern __shared__ char sm2[];
    uint32_t base = smem_u32(sm2);
    uint32_t AsO[NSTAGE], BsO[NSTAGE];
    #pragma unroll
    for (int s = 0; s < NSTAGE; s++) {
        AsO[s] = base + (uint32_t)s * 2 * STAGE2_BYTES;
        BsO[s] = AsO[s] + STAGE2_BYTES;
    }

    const int tid  = threadIdx.x;
    const int wid  = tid >> 5;
    const int lane = tid & 31;
    const int g    = lane >> 2;
    const int t    = lane & 3;
    const int wm   = (wid >> 2) * 64;
    const int wn   = (wid & 3) * 32;

    const int rowBase = blockIdx.y * BM;
    const int colBase = blockIdx.x * BN;
    const int NK = K / BK;               // 32 (even)

    const __nv_bfloat16* Abase = A  + (size_t)rowBase * K;
    const __nv_bfloat16* Bbase = Bt + (size_t)colBase * K;

    float acc[4][4][4];
    #pragma unroll
    for (int i = 0; i < 4; i++)
        #pragma unroll
        for (int j = 0; j < 4; j++)
            #pragma unroll
            for (int r = 0; r < 4; r++) acc[i][j][r] = 0.f;

    auto load_stage = [&](int st, int k0) {
        #pragma unroll
        for (int i = 0; i < 2; i++) {
            int idx = tid + i * 256;        // 0..511
            int r   = idx >> 2;             // 0..127
            int c   = idx & 3;              // 16B chunk
            uint32_t off = (uint32_t)(r * (KP2 * 2) + c * 16);
            cp_async16(AsO[st] + off, Abase + (size_t)r * K + k0 + c * 8);
            cp_async16(BsO[st] + off, Bbase + (size_t)r * K + k0 + c * 8);
        }
        cp_commit();
    };

    // ldmatrix per-thread address components
    const uint32_t aRowOff = (uint32_t)(lane & 15) * (KP2 * 2);
    const uint32_t aKh     = (uint32_t)(lane >> 4) * 16;
    const uint32_t bRowOff = (uint32_t)((lane & 7) + ((lane >> 4) << 3)) * (KP2 * 2);
    const uint32_t bKh     = (uint32_t)((lane >> 3) & 1) * 16;

    // two fragment register sets (ping-pong)
    uint32_t afr0[4][4], bfr0[4][2];
    uint32_t afr1[4][4], bfr1[4][2];

    auto load_frags = [&](uint32_t (&fa)[4][4], uint32_t (&fb)[4][2],
                          uint32_t as, uint32_t bs, uint32_t kb) {
        #pragma unroll
        for (int mt = 0; mt < 4; mt++)
            ldsm_x4(fa[mt][0], fa[mt][1], fa[mt][2], fa[mt][3],
                    as + (uint32_t)(wm + mt * 16) * (KP2 * 2) + aRowOff + kb + aKh);
        #pragma unroll
        for (int p = 0; p < 2; p++) {
            uint32_t r0, r1, r2, r3;
            ldsm_x4(r0, r1, r2, r3,
                    bs + (uint32_t)(wn + p * 16) * (KP2 * 2) + bRowOff + kb + bKh);
            fb[2 * p][0]     = r0; fb[2 * p][1]     = r1;
            fb[2 * p + 1][0] = r2; fb[2 * p + 1][1] = r3;
        }
    };
    auto mma_all = [&](uint32_t (&fa)[4][4], uint32_t (&fb)[4][2]) {
        #pragma unroll
        for (int mt = 0; mt < 4; mt++)
            #pragma unroll
            for (int nt = 0; nt < 4; nt++)
                mma_bf16(acc[mt][nt][0], acc[mt][nt][1],
                         acc[mt][nt][2], acc[mt][nt][3],
                         fa[mt][0], fa[mt][1], fa[mt][2], fa[mt][3],
                         fb[nt][0], fb[nt][1]);
    };

    // prologue: stages 0,1,2  (3 groups in flight)
    load_stage(0, 0);
    load_stage(1, BK);
    load_stage(2, 2 * BK);

    for (int j = 0; j < NK; j += 2) {
        if (j + 2 < NK) { cp_wait<1>(); }
        else            { cp_wait<0>(); }
        __syncthreads();

        if (j + 3 < NK) load_stage((j + 3) % NSTAGE, (j + 3) * BK);
        if (j + 4 < NK) load_stage((j + 4) % NSTAGE, (j + 4) * BK);

        uint32_t asJ  = AsO[j % NSTAGE],       bsJ  = BsO[j % NSTAGE];
        uint32_t asJ1 = AsO[(j + 1) % NSTAGE], bsJ1 = BsO[(j + 1) % NSTAGE];

        load_frags(afr0, bfr0, asJ,  bsJ,  0);
        load_frags(afr1, bfr1, asJ,  bsJ,  32);
        mma_all(afr0, bfr0);
        load_frags(afr0, bfr0, asJ1, bsJ1, 0);
        mma_all(afr1, bfr1);
        load_frags(afr1, bfr1, asJ1, bsJ1, 32);
        mma_all(afr0, bfr0);
        mma_all(afr1, bfr1);
    }

    // epilogue -> bf16 out
    #pragma unroll
    for (int mt = 0; mt < 4; mt++) {
        int row0 = rowBase + wm + mt * 16 + g;
        __nv_bfloat16* crow0 = C + (size_t)row0 * Nreal;
        __nv_bfloat16* crow1 = C + (size_t)(row0 + 8) * Nreal;
        #pragma unroll
        for (int nt = 0; nt < 4; nt++) {
            int col0 = colBase + wn + nt * 8 + 2 * t;
            if (col0 + 1 < Nreal) {
                float b0 = bias[col0], b1 = bias[col0 + 1];
                float v0 = acc[mt][nt][0] + b0;
                float v1 = acc[mt][nt][1] + b1;
                float v2 = acc[mt][nt][2] + b0;
                float v3 = acc[mt][nt][3] + b1;
                if constexpr (EPI == 0) {
                    v0 = gelu_tanh(v0); v1 = gelu_tanh(v1);
                    v2 = gelu_tanh(v2); v3 = gelu_tanh(v3);
                }
                __nv_bfloat162 p0, p1;
                p0.x = __float2bfloat16_rn(v0); p0.y = __float2bfloat16_rn(v1);
                p1.x = __float2bfloat16_rn(v2); p1.y = __float2bfloat16_rn(v3);
                *(__nv_bfloat162*)&crow0[col0] = p0;
                *(__nv_bfloat162*)&crow1[col0] = p1;
            } else if (col0 < Nreal) {
                float b0 = bias[col0];
                float v0 = acc[mt][nt][0] + b0;
                float v2 = acc[mt][nt][2] + b0;
                if constexpr (EPI == 0) { v0 = gelu_tanh(v0); v2 = gelu_tanh(v2); }
                crow0[col0] = __float2bfloat16_rn(v0);
                crow1[col0] = __float2bfloat16_rn(v2);
            }
        }
    }
}

// ---------------------------------------------------------------------------
// per-row softmax * p_gen + shared-memory scatter-add, write fp32 out.
// Reads bf16 logits (V=5000 -> 625 uint4 chunks of 8 bf16).
// ---------------------------------------------------------------------------
#define SMT 512
__global__ __launch_bounds__(SMT)
void softmax_scatter_kernel(const __nv_bfloat16* __restrict__ logits,
                            const float* __restrict__ attn,
                            const int*   __restrict__ nodes,
                            const float* __restrict__ pgen,
                            float* __restrict__ out) {
    __shared__ float srow[V_];
    __shared__ float red[17];

    const int r   = blockIdx.x;
    const int b   = r / T_;
    const int tid = threadIdx.x;
    const __nv_bfloat16* lrow = logits + (size_t)r * V_;
    float* orow   = out + (size_t)r * V_;
    const int nwarp = SMT / 32;

    // load bf16 logits -> fp32 smem, local max (8 values per 16B load)
    float mx = -3.0e38f;
    for (int i = tid; i < V_ / 8; i += SMT) {
        uint4 u = ((const uint4*)lrow)[i];
        float2 f0 = __bfloat1622float2(*(__nv_bfloat162*)&u.x);
        float2 f1 = __bfloat1622float2(*(__nv_bfloat162*)&u.y);
        float2 f2 = __bfloat1622float2(*(__nv_bfloat162*)&u.z);
        float2 f3 = __bfloat1622float2(*(__nv_bfloat162*)&u.w);
        float2* s2 = (float2*)&srow[i * 8];
        s2[0] = f0; s2[1] = f1; s2[2] = f2; s2[3] = f3;
        mx = fmaxf(mx, fmaxf(fmaxf(f0.x, f0.y), fmaxf(f1.x, f1.y)));
        mx = fmaxf(mx, fmaxf(fmaxf(f2.x, f2.y), fmaxf(f3.x, f3.y)));
    }
    #pragma unroll
    for (int o = 16; o; o >>= 1) mx = fmaxf(mx, __shfl_xor_sync(0xFFFFFFFFu, mx, o));
    if ((tid & 31) == 0) red[tid >> 5] = mx;
    __syncthreads();
    if (tid < nwarp) {
        float v = red[tid];
        #pragma unroll
        for (int o = 8; o; o >>= 1) v = fmaxf(v, __shfl_xor_sync(0xFFFFu, v, o));
        if (tid == 0) red[16] = v;
    }
    __syncthreads();
    mx = red[16];

    // exp + local sum
    float sum = 0.f;
    for (int i = tid; i < V_ / 4; i += SMT) {
        float4 v = ((float4*)srow)[i];
        v.x = __expf(v.x - mx); v.y = __expf(v.y - mx);
        v.z = __expf(v.z - mx); v.w = __expf(v.w - mx);
        ((float4*)srow)[i] = v;
        sum += v.x + v.y + v.z + v.w;
    }
    __syncthreads();
    #pragma unroll
    for (int o = 16; o; o >>= 1) sum += __shfl_xor_sync(0xFFFFFFFFu, sum, o);
    if ((tid & 31) == 0) red[tid >> 5] = sum;
    __syncthreads();
    if (tid < nwarp) {
        float v = red[tid];
        #pragma unroll
        for (int o = 8; o; o >>= 1) v += __shfl_xor_sync(0xFFFFu, v, o);
        if (tid == 0) red[16] = v;
    }
    __syncthreads();
    sum = red[16];

    const float pg    = pgen[r];
    const float scale = pg / sum;                 // final multiplier
    const float caddf = (1.f - pg) * sum / pg;    // pre-divided pointer mass

    const float* ar = attn  + (size_t)r * S_;
    const int*   nb = nodes + (size_t)b * S_;
    for (int i = tid; i < S_ / 4; i += SMT) {
        float4 av = ((const float4*)ar)[i];
        int4   nv = ((const int4*)nb)[i];
        atomicAdd(&srow[nv.x], av.x * caddf);
        atomicAdd(&srow[nv.y], av.y * caddf);
        atomicAdd(&srow[nv.z], av.z * caddf);
        atomicAdd(&srow[nv.w], av.w * caddf);
    }
    __syncthreads();

    for (int i = tid; i < V_ / 4; i += SMT) {
        float4 v = ((const float4*)srow)[i];
        v.x *= scale; v.y *= scale; v.z *= scale; v.w *= scale;
        ((float4*)orow)[i] = v;
    }
}

// ---------------------------------------------------------------------------
// Launch
// ---------------------------------------------------------------------------
extern "C" void kernel_launch(void* const* d_in, const int* in_sizes, int n_in,
                              void* d_out, int out_size) {
    const float* x    = (const float*)d_in[0];
    const float* attn = (const float*)d_in[1];
    const int*   nodes= (const int*)  d_in[2];
    const float* Wg   = (const float*)d_in[3];
    const float* bg   = (const float*)d_in[4];
    const float* Wf   = (const float*)d_in[5];
    const float* bf   = (const float*)d_in[6];
    const float* Wv   = (const float*)d_in[7];
    const float* bv   = (const float*)d_in[8];
    float* out        = (float*)d_out;

    __nv_bfloat16* xb;   cudaGetSymbolAddress((void**)&xb,   g_xb);
    __nv_bfloat16* hb;   cudaGetSymbolAddress((void**)&hb,   g_hb);
    __nv_bfloat16* lb;   cudaGetSymbolAddress((void**)&lb,   g_lb);
    float* pgen;         cudaGetSymbolAddress((void**)&pgen, g_pgen);
    __nv_bfloat16* WfTb; cudaGetSymbolAddress((void**)&WfTb, g_WfTb);
    __nv_bfloat16* WvTb; cudaGetSymbolAddress((void**)&WvTb, g_WvTb);

    cudaFuncSetAttribute((const void*)bf16_gemm_kernel<0>,
                         cudaFuncAttributeMaxDynamicSharedMemorySize, DYNSMEM2);
    cudaFuncSetAttribute((const void*)bf16_gemm_kernel<1>,
                         cudaFuncAttributeMaxDynamicSharedMemorySize, DYNSMEM2);

    // prep: weight transposes (bf16, K-major)
    transpose_bf16_kernel<<<dim3(H_ / 32, H_ / 32), dim3(32, 8)>>>(Wf, WfTb, H_, H_, H_);
    transpose_bf16_kernel<<<dim3(VPAD / 32, H_ / 32), dim3(32, 8)>>>(Wv, WvTb, H_, V_, VPAD);

    // p_gen (fp32 dot) + x -> bf16 (fused)
    pgen_cvt_kernel<<<M_, 256>>>(x, Wg, bg, pgen, xb);

    // h_bf16 = gelu(x @ Wf + bf)
    bf16_gemm_kernel<0><<<dim3(H_ / BN, M_ / BM), 256, DYNSMEM2>>>(
        xb, WfTb, bf, hb, H_, H_);

    // logits_bf16 = h_bf @ Wv + bv -> g_lb
    bf16_gemm_kernel<1><<<dim3(VPAD / BN, M_ / BM), 256, DYNSMEM2>>>(
        hb, WvTb, bv, lb, V_, H_);

    // softmax * p_gen + pointer scatter (bf16 logits in, fp32 out)
    softmax_scatter_kernel<<<M_, SMT>>>(lb, attn, nodes, pgen, out);
}

// round 17
// speedup vs baseline: 1.1223x; 1.0171x over previous
#include <cuda_runtime.h>
#include <cuda_bf16.h>
#include <cstdint>

// Problem constants
#define B_  8
#define T_  1024
#define S_  1024
#define H_  1024
#define V_  5000
#define M_  (B_ * T_)   // 8192 rows
#define VPAD 5120       // V padded to multiple of 128

// Scratch (static device globals — allocation-free)
__device__ __nv_bfloat16 g_xb[(size_t)M_ * H_];    // x in bf16, 16 MB
__device__ __nv_bfloat16 g_hb[(size_t)M_ * H_];    // gelu(x@Wf+bf) in bf16, 16 MB
__device__ __nv_bfloat16 g_lb[(size_t)M_ * V_];    // logits bf16, 78 MB
__device__ float g_pgen[M_];                       // sigmoid(x@Wg + bg)
__device__ __nv_bfloat16 g_WfTb[(size_t)H_ * H_];  // Wf^T bf16 [N=H][K=H]
__device__ __nv_bfloat16 g_WvTb[(size_t)VPAD * H_];// Wv^T bf16 [N=VPAD][K=H], padded

// ---------------------------------------------------------------------------
// helpers
// ---------------------------------------------------------------------------
__device__ __forceinline__ uint32_t smem_u32(const void* p) {
    return (uint32_t)__cvta_generic_to_shared(p);
}
__device__ __forceinline__ void cp_async16(uint32_t dst, const void* src) {
    asm volatile("cp.async.cg.shared.global [%0], [%1], 16;" :: "r"(dst), "l"(src));
}
__device__ __forceinline__ void cp_commit() {
    asm volatile("cp.async.commit_group;" ::: "memory");
}
template <int N>
__device__ __forceinline__ void cp_wait() {
    asm volatile("cp.async.wait_group %0;" :: "n"(N) : "memory");
}

// m16n8k16 bf16 mma (sm_80+)
__device__ __forceinline__ void mma_bf16(float& d0, float& d1, float& d2, float& d3,
                                         uint32_t a0, uint32_t a1, uint32_t a2, uint32_t a3,
                                         uint32_t b0, uint32_t b1) {
    asm volatile(
        "mma.sync.aligned.m16n8k16.row.col.f32.bf16.bf16.f32 "
        "{%0,%1,%2,%3}, {%4,%5,%6,%7}, {%8,%9}, {%0,%1,%2,%3};"
        : "+f"(d0), "+f"(d1), "+f"(d2), "+f"(d3)
        : "r"(a0), "r"(a1), "r"(a2), "r"(a3), "r"(b0), "r"(b1));
}

__device__ __forceinline__ void ldsm_x4(uint32_t& r0, uint32_t& r1, uint32_t& r2, uint32_t& r3,
                                        uint32_t addr) {
    asm volatile("ldmatrix.sync.aligned.m8n8.x4.shared.b16 {%0,%1,%2,%3}, [%4];"
                 : "=r"(r0), "=r"(r1), "=r"(r2), "=r"(r3) : "r"(addr));
}

__device__ __forceinline__ float gelu_tanh(float v) {
    const float c = 0.7978845608028654f;   // sqrt(2/pi)
    float u = c * (v + 0.044715f * v * v * v);
    return 0.5f * v * (1.f + tanhf(u));
}

// ---------------------------------------------------------------------------
// Fused prep kernel (ONE launch, blocks partitioned):
//   blocks [0, NB_WF)            : Wf^T bf16 transpose tiles (32x32)
//   blocks [NB_WF, NB_WF+NB_WV)  : Wv^T bf16 transpose tiles (zero-padded rows)
//   blocks [.., +M_)             : per-row p_gen + x->bf16 conversion
// 256 threads everywhere.
// ---------------------------------------------------------------------------
#define NB_WF ((H_ / 32) * (H_ / 32))          // 1024
#define NB_WV ((VPAD / 32) * (H_ / 32))        // 5120
#define NB_PREP (NB_WF + NB_WV + M_)           // 14336

__device__ __forceinline__ void transpose_tile(const float* __restrict__ W,
                                               __nv_bfloat16* __restrict__ Wt,
                                               int R, int C, int Cpad,
                                               int c0, int r0, int tx, int ty) {
    __shared__ float t[32][33];
    #pragma unroll
    for (int k = 0; k < 4; k++) {
        int r = r0 + ty + k * 8;
        int c = c0 + tx;
        float v = 0.f;
        if (r < R && c < C) v = W[(size_t)r * C + c];
        t[ty + k * 8][tx] = v;
    }
    __syncthreads();
    #pragma unroll
    for (int k = 0; k < 4; k++) {
        int rr = c0 + ty + k * 8;
        int cc = r0 + tx;
        if (rr < Cpad && cc < R)
            Wt[(size_t)rr * R + cc] = __float2bfloat16_rn(t[tx][ty + k * 8]);
    }
}

__global__ __launch_bounds__(256)
void prep_kernel(const float* __restrict__ x,
                 const float* __restrict__ Wg,
                 const float* __restrict__ bg,
                 const float* __restrict__ Wf,
                 const float* __restrict__ Wv,
                 float* __restrict__ pgen,
                 __nv_bfloat16* __restrict__ xb,
                 __nv_bfloat16* __restrict__ WfTb,
                 __nv_bfloat16* __restrict__ WvTb) {
    const int bid = blockIdx.x;
    const int tid = threadIdx.x;

    if (bid < NB_WF) {
        // Wf transpose: [H][H] -> [H][H] bf16
        int i = bid;
        int c0 = (i % (H_ / 32)) * 32;
        int r0 = (i / (H_ / 32)) * 32;
        transpose_tile(Wf, WfTb, H_, H_, H_, c0, r0, tid & 31, tid >> 5);
        return;
    }
    if (bid < NB_WF + NB_WV) {
        // Wv transpose: [H][V] -> [VPAD][H] bf16, zero-padded
        int i = bid - NB_WF;
        int c0 = (i % (VPAD / 32)) * 32;
        int r0 = (i / (VPAD / 32)) * 32;
        transpose_tile(Wv, WvTb, H_, V_, VPAD, c0, r0, tid & 31, tid >> 5);
        return;
    }

    // p_gen + x -> bf16 for one row
    int r = bid - NB_WF - NB_WV;
    const float* xr = x + (size_t)r * H_;
    __nv_bfloat16* xbr = xb + (size_t)r * H_;

    float s = 0.f;
    for (int i = tid; i < H_ / 4; i += 256) {
        float4 v = ((const float4*)xr)[i];
        float4 w = ((const float4*)Wg)[i];
        s += v.x * w.x + v.y * w.y + v.z * w.z + v.w * w.w;
        __nv_bfloat162 p0, p1;
        p0.x = __float2bfloat16_rn(v.x); p0.y = __float2bfloat16_rn(v.y);
        p1.x = __float2bfloat16_rn(v.z); p1.y = __float2bfloat16_rn(v.w);
        ((__nv_bfloat162*)xbr)[2 * i]     = p0;
        ((__nv_bfloat162*)xbr)[2 * i + 1] = p1;
    }
    __shared__ float red[8];
    #pragma unroll
    for (int o = 16; o; o >>= 1) s += __shfl_xor_sync(0xFFFFFFFFu, s, o);
    if ((tid & 31) == 0) red[tid >> 5] = s;
    __syncthreads();
    if (tid < 8) {
        s = red[tid];
        #pragma unroll
        for (int o = 4; o; o >>= 1) s += __shfl_xor_sync(0xFFu, s, o);
        if (tid == 0) {
            float z = s + bg[0];
            pgen[r] = 1.f / (1.f + expf(-z));
        }
    }
}

// ---------------------------------------------------------------------------
// bf16 mma.sync GEMM (best config): C = epi(A[M,K] @ Bt[N,K]^T + bias[N])
// BM=BN=128, BK=32 bf16, 256 threads (8 warps 2x4), warp tile 64x32.
// 5-stage cp.async ring, one wait+sync per TWO k-iterations, k16 ping-pong.
// SMEM rows padded to 40 bf16 -> conflict-free LDSM.
// EPI 0: gelu -> bf16 out.  EPI 1: bias only -> bf16 out (ragged N).
// ---------------------------------------------------------------------------
#define BM 128
#define BN 128
#define BK 32
#define KP2 40
#define STAGE2_BYTES (128 * KP2 * 2)          // 10240 B per operand per stage
#define NSTAGE 5
#define DYNSMEM2 (NSTAGE * 2 * STAGE2_BYTES)  // 102400 B (2 CTAs = 204.8 KB/SM)

template <int EPI>
__global__ __launch_bounds__(256, 2)
void bf16_gemm_kernel(const __nv_bfloat16* __restrict__ A,
                      const __nv_bfloat16* __restrict__ Bt,
                      const float* __restrict__ bias, __nv_bfloat16* __restrict__ C,
                      int Nreal, int K) {
    extern __shared__ char sm2[];
    uint32_t base = smem_u32(sm2);
    uint32_t AsO[NSTAGE], BsO[NSTAGE];
    #pragma unroll
    for (int s = 0; s < NSTAGE; s++) {
        AsO[s] = base + (uint32_t)s * 2 * STAGE2_BYTES;
        BsO[s] = AsO[s] + STAGE2_BYTES;
    }

    const int tid  = threadIdx.x;
    const int wid  = tid >> 5;
    const int lane = tid & 31;
    const int g    = lane >> 2;
    const int t    = lane & 3;
    const int wm   = (wid >> 2) * 64;
    const int wn   = (wid & 3) * 32;

    const int rowBase = blockIdx.y * BM;
    const int colBase = blockIdx.x * BN;
    const int NK = K / BK;               // 32 (even)

    const __nv_bfloat16* Abase = A  + (size_t)rowBase * K;
    const __nv_bfloat16* Bbase = Bt + (size_t)colBase * K;

    float acc[4][4][4];
    #pragma unroll
    for (int i = 0; i < 4; i++)
        #pragma unroll
        for (int j = 0; j < 4; j++)
            #pragma unroll
            for (int r = 0; r < 4; r++) acc[i][j][r] = 0.f;

    auto load_stage = [&](int st, int k0) {
        #pragma unroll
        for (int i = 0; i < 2; i++) {
            int idx = tid + i * 256;        // 0..511
            int r   = idx >> 2;             // 0..127
            int c   = idx & 3;              // 16B chunk
            uint32_t off = (uint32_t)(r * (KP2 * 2) + c * 16);
            cp_async16(AsO[st] + off, Abase + (size_t)r * K + k0 + c * 8);
            cp_async16(BsO[st] + off, Bbase + (size_t)r * K + k0 + c * 8);
        }
        cp_commit();
    };

    // ldmatrix per-thread address components
    const uint32_t aRowOff = (uint32_t)(lane & 15) * (KP2 * 2);
    const uint32_t aKh     = (uint32_t)(lane >> 4) * 16;
    const uint32_t bRowOff = (uint32_t)((lane & 7) + ((lane >> 4) << 3)) * (KP2 * 2);
    const uint32_t bKh     = (uint32_t)((lane >> 3) & 1) * 16;

    // two fragment register sets (ping-pong)
    uint32_t afr0[4][4], bfr0[4][2];
    uint32_t afr1[4][4], bfr1[4][2];

    auto load_frags = [&](uint32_t (&fa)[4][4], uint32_t (&fb)[4][2],
                          uint32_t as, uint32_t bs, uint32_t kb) {
        #pragma unroll
        for (int mt = 0; mt < 4; mt++)
            ldsm_x4(fa[mt][0], fa[mt][1], fa[mt][2], fa[mt][3],
                    as + (uint32_t)(wm + mt * 16) * (KP2 * 2) + aRowOff + kb + aKh);
        #pragma unroll
        for (int p = 0; p < 2; p++) {
            uint32_t r0, r1, r2, r3;
            ldsm_x4(r0, r1, r2, r3,
                    bs + (uint32_t)(wn + p * 16) * (KP2 * 2) + bRowOff + kb + bKh);
            fb[2 * p][0]     = r0; fb[2 * p][1]     = r1;
            fb[2 * p + 1][0] = r2; fb[2 * p + 1][1] = r3;
        }
    };
    auto mma_all = [&](uint32_t (&fa)[4][4], uint32_t (&fb)[4][2]) {
        #pragma unroll
        for (int mt = 0; mt < 4; mt++)
            #pragma unroll
            for (int nt = 0; nt < 4; nt++)
                mma_bf16(acc[mt][nt][0], acc[mt][nt][1],
                         acc[mt][nt][2], acc[mt][nt][3],
                         fa[mt][0], fa[mt][1], fa[mt][2], fa[mt][3],
                         fb[nt][0], fb[nt][1]);
    };

    // prologue: stages 0,1,2  (3 groups in flight)
    load_stage(0, 0);
    load_stage(1, BK);
    load_stage(2, 2 * BK);

    for (int j = 0; j < NK; j += 2) {
        if (j + 2 < NK) { cp_wait<1>(); }
        else            { cp_wait<0>(); }
        __syncthreads();

        if (j + 3 < NK) load_stage((j + 3) % NSTAGE, (j + 3) * BK);
        if (j + 4 < NK) load_stage((j + 4) % NSTAGE, (j + 4) * BK);

        uint32_t asJ  = AsO[j % NSTAGE],       bsJ  = BsO[j % NSTAGE];
        uint32_t asJ1 = AsO[(j + 1) % NSTAGE], bsJ1 = BsO[(j + 1) % NSTAGE];

        load_frags(afr0, bfr0, asJ,  bsJ,  0);
        load_frags(afr1, bfr1, asJ,  bsJ,  32);
        mma_all(afr0, bfr0);
        load_frags(afr0, bfr0, asJ1, bsJ1, 0);
        mma_all(afr1, bfr1);
        load_frags(afr1, bfr1, asJ1, bsJ1, 32);
        mma_all(afr0, bfr0);
        mma_all(afr1, bfr1);
    }

    // epilogue -> bf16 out
    #pragma unroll
    for (int mt = 0; mt < 4; mt++) {
        int row0 = rowBase + wm + mt * 16 + g;
        __nv_bfloat16* crow0 = C + (size_t)row0 * Nreal;
        __nv_bfloat16* crow1 = C + (size_t)(row0 + 8) * Nreal;
        #pragma unroll
        for (int nt = 0; nt < 4; nt++) {
            int col0 = colBase + wn + nt * 8 + 2 * t;
            if (col0 + 1 < Nreal) {
                float b0 = bias[col0], b1 = bias[col0 + 1];
                float v0 = acc[mt][nt][0] + b0;
                float v1 = acc[mt][nt][1] + b1;
                float v2 = acc[mt][nt][2] + b0;
                float v3 = acc[mt][nt][3] + b1;
                if constexpr (EPI == 0) {
                    v0 = gelu_tanh(v0); v1 = gelu_tanh(v1);
                    v2 = gelu_tanh(v2); v3 = gelu_tanh(v3);
                }
                __nv_bfloat162 p0, p1;
                p0.x = __float2bfloat16_rn(v0); p0.y = __float2bfloat16_rn(v1);
                p1.x = __float2bfloat16_rn(v2); p1.y = __float2bfloat16_rn(v3);
                *(__nv_bfloat162*)&crow0[col0] = p0;
                *(__nv_bfloat162*)&crow1[col0] = p1;
            } else if (col0 < Nreal) {
                float b0 = bias[col0];
                float v0 = acc[mt][nt][0] + b0;
                float v2 = acc[mt][nt][2] + b0;
                if constexpr (EPI == 0) { v0 = gelu_tanh(v0); v2 = gelu_tanh(v2); }
                crow0[col0] = __float2bfloat16_rn(v0);
                crow1[col0] = __float2bfloat16_rn(v2);
            }
        }
    }
}

// ---------------------------------------------------------------------------
// per-row softmax * p_gen + shared-memory scatter-add, write fp32 out.
// Reads bf16 logits (V=5000 -> 625 uint4 chunks of 8 bf16).
// ---------------------------------------------------------------------------
#define SMT 512
__global__ __launch_bounds__(SMT)
void softmax_scatter_kernel(const __nv_bfloat16* __restrict__ logits,
                            const float* __restrict__ attn,
                            const int*   __restrict__ nodes,
                            const float* __restrict__ pgen,
                            float* __restrict__ out) {
    __shared__ float srow[V_];
    __shared__ float red[17];

    const int r   = blockIdx.x;
    const int b   = r / T_;
    const int tid = threadIdx.x;
    const __nv_bfloat16* lrow = logits + (size_t)r * V_;
    float* orow   = out + (size_t)r * V_;
    const int nwarp = SMT / 32;

    // load bf16 logits -> fp32 smem, local max (8 values per 16B load)
    float mx = -3.0e38f;
    for (int i = tid; i < V_ / 8; i += SMT) {
        uint4 u = ((const uint4*)lrow)[i];
        float2 f0 = __bfloat1622float2(*(__nv_bfloat162*)&u.x);
        float2 f1 = __bfloat1622float2(*(__nv_bfloat162*)&u.y);
        float2 f2 = __bfloat1622float2(*(__nv_bfloat162*)&u.z);
        float2 f3 = __bfloat1622float2(*(__nv_bfloat162*)&u.w);
        float2* s2 = (float2*)&srow[i * 8];
        s2[0] = f0; s2[1] = f1; s2[2] = f2; s2[3] = f3;
        mx = fmaxf(mx, fmaxf(fmaxf(f0.x, f0.y), fmaxf(f1.x, f1.y)));
        mx = fmaxf(mx, fmaxf(fmaxf(f2.x, f2.y), fmaxf(f3.x, f3.y)));
    }
    #pragma unroll
    for (int o = 16; o; o >>= 1) mx = fmaxf(mx, __shfl_xor_sync(0xFFFFFFFFu, mx, o));
    if ((tid & 31) == 0) red[tid >> 5] = mx;
    __syncthreads();
    if (tid < nwarp) {
        float v = red[tid];
        #pragma unroll
        for (int o = 8; o; o >>= 1) v = fmaxf(v, __shfl_xor_sync(0xFFFFu, v, o));
        if (tid == 0) red[16] = v;
    }
    __syncthreads();
    mx = red[16];

    // exp + local sum
    float sum = 0.f;
    for (int i = tid; i < V_ / 4; i += SMT) {
        float4 v = ((float4*)srow)[i];
        v.x = __expf(v.x - mx); v.y = __expf(v.y - mx);
        v.z = __expf(v.z - mx); v.w = __expf(v.w - mx);
        ((float4*)srow)[i] = v;
        sum += v.x + v.y + v.z + v.w;
    }
    __syncthreads();
    #pragma unroll
    for (int o = 16; o; o >>= 1) sum += __shfl_xor_sync(0xFFFFFFFFu, sum, o);
    if ((tid & 31) == 0) red[tid >> 5] = sum;
    __syncthreads();
    if (tid < nwarp) {
        float v = red[tid];
        #pragma unroll
        for (int o = 8; o; o >>= 1) v += __shfl_xor_sync(0xFFFFu, v, o);
        if (tid == 0) red[16] = v;
    }
    __syncthreads();
    sum = red[16];

    const float pg    = pgen[r];
    const float scale = pg / sum;                 // final multiplier
    const float caddf = (1.f - pg) * sum / pg;    // pre-divided pointer mass

    const float* ar = attn  + (size_t)r * S_;
    const int*   nb = nodes + (size_t)b * S_;
    for (int i = tid; i < S_ / 4; i += SMT) {
        float4 av = ((const float4*)ar)[i];
        int4   nv = ((const int4*)nb)[i];
        atomicAdd(&srow[nv.x], av.x * caddf);
        atomicAdd(&srow[nv.y], av.y * caddf);
        atomicAdd(&srow[nv.z], av.z * caddf);
        atomicAdd(&srow[nv.w], av.w * caddf);
    }
    __syncthreads();

    for (int i = tid; i < V_ / 4; i += SMT) {
        float4 v = ((const float4*)srow)[i];
        v.x *= scale; v.y *= scale; v.z *= scale; v.w *= scale;
        ((float4*)orow)[i] = v;
    }
}

// ---------------------------------------------------------------------------
// Launch
// ---------------------------------------------------------------------------
extern "C" void kernel_launch(void* const* d_in, const int* in_sizes, int n_in,
                              void* d_out, int out_size) {
    const float* x    = (const float*)d_in[0];
    const float* attn = (const float*)d_in[1];
    const int*   nodes= (const int*)  d_in[2];
    const float* Wg   = (const float*)d_in[3];
    const float* bg   = (const float*)d_in[4];
    const float* Wf   = (const float*)d_in[5];
    const float* bf   = (const float*)d_in[6];
    const float* Wv   = (const float*)d_in[7];
    const float* bv   = (const float*)d_in[8];
    float* out        = (float*)d_out;

    __nv_bfloat16* xb;   cudaGetSymbolAddress((void**)&xb,   g_xb);
    __nv_bfloat16* hb;   cudaGetSymbolAddress((void**)&hb,   g_hb);
    __nv_bfloat16* lb;   cudaGetSymbolAddress((void**)&lb,   g_lb);
    float* pgen;         cudaGetSymbolAddress((void**)&pgen, g_pgen);
    __nv_bfloat16* WfTb; cudaGetSymbolAddress((void**)&WfTb, g_WfTb);
    __nv_bfloat16* WvTb; cudaGetSymbolAddress((void**)&WvTb, g_WvTb);

    cudaFuncSetAttribute((const void*)bf16_gemm_kernel<0>,
                         cudaFuncAttributeMaxDynamicSharedMemorySize, DYNSMEM2);
    cudaFuncSetAttribute((const void*)bf16_gemm_kernel<1>,
                         cudaFuncAttributeMaxDynamicSharedMemorySize, DYNSMEM2);

    // ONE fused prep launch: Wf^T, Wv^T (bf16, K-major) + p_gen + x->bf16
    prep_kernel<<<NB_PREP, 256>>>(x, Wg, bg, Wf, Wv, pgen, xb, WfTb, WvTb);

    // h_bf16 = gelu(x @ Wf + bf)
    bf16_gemm_kernel<0><<<dim3(H_ / BN, M_ / BM), 256, DYNSMEM2>>>(
        xb, WfTb, bf, hb, H_, H_);

    // logits_bf16 = h_bf @ Wv + bv -> g_lb
    bf16_gemm_kernel<1><<<dim3(VPAD / BN, M_ / BM), 256, DYNSMEM2>>>(
        hb, WvTb, bv, lb, V_, H_);

    // softmax * p_gen + pointer scatter (bf16 logits in, fp32 out)
    softmax_scatter_kernel<<<M_, SMT>>>(lb, attn, nodes, pgen, out);
}